// round 10
// baseline (speedup 1.0000x reference)
#include <cuda_runtime.h>
#include <cuda_bf16.h>
#include <cstdint>

#define BATCH 8192
#define DFEAT 784
#define KPAD  832          // 13 * 64 int8 elements
#define KC    64           // int8 elements per stage chunk (64B rows)
#define NC    13
#define TM    128
#define TN    128
#define STAGES 3
#define NTILE 2080         // 64*65/2 upper-triangular 128x128 tiles

#define A_STAGE_BYTES 8192          // 128 rows * 64 B
#define B_STAGE_BYTES 8192
#define STAGE_BYTES   (A_STAGE_BYTES + B_STAGE_BYTES)
#define SMEM_DYN      (STAGES * STAGE_BYTES)

#define QSCALE   256.0f
#define INV_S2   (1.0f / (QSCALE * QSCALE))

__device__ unsigned char g_q[(size_t)BATCH * KPAD];

// ---------------------------------------------------------------------------
// Kernel A (warp-per-image): conv(2x2,s2)+bias -> groupwise 4x4 unitary
//  -> row norm -> int8 qn scratch (scale 256); linear head -> log_softmax
// ---------------------------------------------------------------------------
__global__ __launch_bounds__(256) void prep_kernel(
    const float* __restrict__ x, const float* __restrict__ conv_w,
    const float* __restrict__ conv_b, const float* __restrict__ unitary,
    const float* __restrict__ lin_w, const float* __restrict__ lin_b,
    float* __restrict__ out_logp)
{
    __shared__ float lw[7840];        // 10 x 784 linear weights
    __shared__ float xs[8][784];      // per-warp image buffer
    __shared__ float cw[16];
    __shared__ float cb[4];
    __shared__ float U[16];
    __shared__ float lb[10];

    const int tid  = threadIdx.x;
    const int lane = tid & 31;
    const int wid  = tid >> 5;

    for (int i = tid; i < 7840; i += 256) lw[i] = lin_w[i];
    if (tid < 16)               cw[tid]      = conv_w[tid];
    if (tid >= 32 && tid < 36)  cb[tid - 32] = conv_b[tid - 32];
    if (tid >= 64 && tid < 80)  U[tid - 64]  = unitary[tid - 64];
    if (tid >= 96 && tid < 106) lb[tid - 96] = lin_b[tid - 96];
    __syncthreads();

    const int b = blockIdx.x * 8 + wid;

    {
        const float4* x4 = reinterpret_cast<const float4*>(x + (size_t)b * 784);
        float4* s4 = reinterpret_cast<float4*>(xs[wid]);
        for (int i = lane; i < 196; i += 32) s4[i] = x4[i];
    }
    __syncwarp();

    float qv[7][4];
    float ss = 0.f;
    {
        int ng = 0;
        for (int g = lane; g < 196; g += 32, ++ng) {
            const int o  = (4 * g) / 196;
            const int p0 = 4 * g - o * 196;
            float f[4];
#pragma unroll
            for (int u = 0; u < 4; ++u) {
                int p = p0 + u;
                int i = p / 14;
                int j = p - 14 * i;
                const float* xr = xs[wid] + (2 * i) * 28 + 2 * j;
                f[u] = cb[o] + cw[o*4+0]*xr[0]  + cw[o*4+1]*xr[1]
                             + cw[o*4+2]*xr[28] + cw[o*4+3]*xr[29];
            }
#pragma unroll
            for (int w = 0; w < 4; ++w) {
                float v = f[0]*U[w*4+0] + f[1]*U[w*4+1]
                        + f[2]*U[w*4+2] + f[3]*U[w*4+3];
                qv[ng][w] = v;
                ss += v * v;
            }
        }
    }
#pragma unroll
    for (int o = 16; o; o >>= 1) ss += __shfl_xor_sync(0xffffffffu, ss, o);
    const float inv = 1.f / (sqrtf(ss) + 1e-12f);

    // int8 quantized normalized store: 4 elems packed per u32
    {
        uint32_t* dst = reinterpret_cast<uint32_t*>(g_q + (size_t)b * KPAD);
        const float qs = inv * QSCALE;
        int ng = 0;
        for (int g = lane; g < 196; g += 32, ++ng) {
            int i0 = __float2int_rn(qv[ng][0] * qs);
            int i1 = __float2int_rn(qv[ng][1] * qs);
            int i2 = __float2int_rn(qv[ng][2] * qs);
            int i3 = __float2int_rn(qv[ng][3] * qs);
            i0 = max(-127, min(127, i0));
            i1 = max(-127, min(127, i1));
            i2 = max(-127, min(127, i2));
            i3 = max(-127, min(127, i3));
            uint32_t pk = (uint32_t)(i0 & 0xff) | ((uint32_t)(i1 & 0xff) << 8)
                        | ((uint32_t)(i2 & 0xff) << 16) | ((uint32_t)(i3 & 0xff) << 24);
            dst[g] = pk;
        }
        if (lane < 12) dst[196 + lane] = 0u;   // pad 784..831
    }

    float part[10];
#pragma unroll
    for (int c = 0; c < 10; ++c) part[c] = 0.f;
    {
        int ng = 0;
        for (int g = lane; g < 196; g += 32, ++ng) {
#pragma unroll
            for (int c = 0; c < 10; ++c) {
                const float4 w4 = *reinterpret_cast<const float4*>(lw + c * 784 + 4 * g);
                part[c] += qv[ng][0]*w4.x + qv[ng][1]*w4.y
                         + qv[ng][2]*w4.z + qv[ng][3]*w4.w;
            }
        }
    }
#pragma unroll
    for (int c = 0; c < 10; ++c) {
#pragma unroll
        for (int o = 16; o; o >>= 1)
            part[c] += __shfl_xor_sync(0xffffffffu, part[c], o);
    }
    if (lane == 0) {
        float lg[10];
#pragma unroll
        for (int c = 0; c < 10; ++c) lg[c] = part[c] + lb[c];
        float mx = lg[0];
#pragma unroll
        for (int c = 1; c < 10; ++c) mx = fmaxf(mx, lg[c]);
        float s = 0.f;
#pragma unroll
        for (int c = 0; c < 10; ++c) s += expf(lg[c] - mx);
        float lse = mx + logf(s);
#pragma unroll
        for (int c = 0; c < 10; ++c) out_logp[(size_t)b * 10 + c] = lg[c] - lse;
    }
}

// ---------------------------------------------------------------------------
// adj kernel: dense triangular grid of 128x128 tiles, 8 warps of 64x32,
// int8 IMMA m16n8k32 s8s8s32, 3-stage cp.async pipeline, 2 CTAs/SM.
// ---------------------------------------------------------------------------
__device__ __forceinline__ void ldsm4(uint32_t& r0, uint32_t& r1,
                                      uint32_t& r2, uint32_t& r3, uint32_t addr)
{
    asm volatile("ldmatrix.sync.aligned.m8n8.x4.shared.b16 {%0,%1,%2,%3}, [%4];"
                 : "=r"(r0), "=r"(r1), "=r"(r2), "=r"(r3) : "r"(addr));
}

__device__ __forceinline__ void mma_s8(int* c, const uint32_t* a, const uint32_t* b)
{
    asm volatile("mma.sync.aligned.m16n8k32.row.col.s32.s8.s8.s32 "
                 "{%0,%1,%2,%3}, {%4,%5,%6,%7}, {%8,%9}, {%0,%1,%2,%3};"
                 : "+r"(c[0]), "+r"(c[1]), "+r"(c[2]), "+r"(c[3])
                 : "r"(a[0]), "r"(a[1]), "r"(a[2]), "r"(a[3]),
                   "r"(b[0]), "r"(b[1]));
}

__device__ __forceinline__ void cpa16(uint32_t s, const void* g) {
    asm volatile("cp.async.cg.shared.global [%0], [%1], 16;" :: "r"(s), "l"(g));
}

__global__ __launch_bounds__(256, 2) void adj_kernel(float* __restrict__ adj)
{
    // decode triangular index -> (br <= bc)
    const int i = blockIdx.x;
    int bc = (int)((sqrtf(8.0f * (float)i + 1.0f) - 1.0f) * 0.5f);
    while ((bc + 1) * (bc + 2) / 2 <= i) ++bc;
    while (bc * (bc + 1) / 2 > i) --bc;
    const int br = i - bc * (bc + 1) / 2;

    extern __shared__ char smem[];
    const uint32_t sBase = (uint32_t)__cvta_generic_to_shared(smem);

    const int tid  = threadIdx.x;
    const int lane = tid & 31;
    const int wid  = tid >> 5;
    const int wm   = wid >> 2;   // 0..1  (64 rows each)
    const int wn   = wid & 3;    // 0..3  (32 cols each)

    int acc[4][4][4];
#pragma unroll
    for (int a = 0; a < 4; a++)
#pragma unroll
        for (int j = 0; j < 4; j++)
#pragma unroll
            for (int k = 0; k < 4; k++) acc[a][j][k] = 0;

    const unsigned char* gA = g_q + (size_t)br * TM * KPAD;
    const unsigned char* gB = g_q + (size_t)bc * TN * KPAD;

    auto load_stage = [&](int s, int c) {
        const uint32_t sa = sBase + s * STAGE_BYTES;
        const uint32_t sb = sa + A_STAGE_BYTES;
        const unsigned char* ga = gA + c * KC;
        const unsigned char* gb = gB + c * KC;
#pragma unroll
        for (int t = 0; t < 2; ++t) {
            int q   = tid + t * 256;
            int row = q >> 2;
            int ch  = q & 3;                 // 16B chunk within 64B row
            int sw  = ch ^ ((row >> 1) & 3);
            uint32_t so = (uint32_t)(row * 64 + sw * 16);
            cpa16(sa + so, ga + (size_t)row * KPAD + ch * 16);
            cpa16(sb + so, gb + (size_t)row * KPAD + ch * 16);
        }
    };

    auto compute = [&](int s) {
        const uint32_t base_a = sBase + s * STAGE_BYTES;
        const uint32_t base_b = base_a + A_STAGE_BYTES;
#pragma unroll
        for (int ks = 0; ks < 2; ++ks) {     // two k32 steps per 64-elem chunk
            uint32_t a[4][4], bb[4][2];
#pragma unroll
            for (int mf = 0; mf < 4; ++mf) {
                int row = wm * 64 + mf * 16 + (lane & 15);
                int c16 = ks * 2 + (lane >> 4);          // 16B-chunk column
                int ch  = c16 ^ ((row >> 1) & 3);
                uint32_t addr = base_a + (uint32_t)(row * 64 + ch * 16);
                ldsm4(a[mf][0], a[mf][1], a[mf][2], a[mf][3], addr);
            }
#pragma unroll
            for (int nf2 = 0; nf2 < 2; ++nf2) {
                int row = wn * 32 + nf2 * 16 + ((lane >> 4) << 3) + (lane & 7);
                int c16 = ks * 2 + ((lane >> 3) & 1);
                int ch  = c16 ^ ((row >> 1) & 3);
                uint32_t addr = base_b + (uint32_t)(row * 64 + ch * 16);
                ldsm4(bb[nf2*2][0], bb[nf2*2][1], bb[nf2*2+1][0], bb[nf2*2+1][1], addr);
            }
#pragma unroll
            for (int mf = 0; mf < 4; ++mf)
#pragma unroll
                for (int nf = 0; nf < 4; ++nf)
                    mma_s8(acc[mf][nf], a[mf], bb[nf]);
        }
    };

    load_stage(0, 0);
    asm volatile("cp.async.commit_group;");
    load_stage(1, 1);
    asm volatile("cp.async.commit_group;");

#pragma unroll 1
    for (int c = 0; c < NC; ++c) {
        if (c < NC - 1) asm volatile("cp.async.wait_group 1;");
        else            asm volatile("cp.async.wait_group 0;");
        __syncthreads();
        if (c + 2 < NC) {
            load_stage((c + 2) % STAGES, c + 2);
            asm volatile("cp.async.commit_group;");
        }
        compute(c % STAGES);
    }

    // epilogue: fid = (acc/S^2)^2, threshold, no self edges; mirror for br<bc
    const int g   = lane >> 2;
    const int tig = lane & 3;
#pragma unroll
    for (int mf = 0; mf < 4; ++mf) {
        const int r0 = br * TM + wm * 64 + mf * 16 + g;
#pragma unroll
        for (int nf = 0; nf < 4; ++nf) {
            const int c0 = bc * TN + wn * 32 + nf * 8 + tig * 2;
            float f0 = (float)acc[mf][nf][0] * INV_S2;
            float f1 = (float)acc[mf][nf][1] * INV_S2;
            float f2 = (float)acc[mf][nf][2] * INV_S2;
            float f3 = (float)acc[mf][nf][3] * INV_S2;
            float v0 = (f0 * f0 >= 0.9f && r0     != c0    ) ? 1.f : 0.f;
            float v1 = (f1 * f1 >= 0.9f && r0     != c0 + 1) ? 1.f : 0.f;
            float v2 = (f2 * f2 >= 0.9f && r0 + 8 != c0    ) ? 1.f : 0.f;
            float v3 = (f3 * f3 >= 0.9f && r0 + 8 != c0 + 1) ? 1.f : 0.f;
            *reinterpret_cast<float2*>(&adj[(size_t)r0 * BATCH + c0]) =
                make_float2(v0, v1);
            *reinterpret_cast<float2*>(&adj[(size_t)(r0 + 8) * BATCH + c0]) =
                make_float2(v2, v3);
            if (br != bc) {
                adj[(size_t)c0       * BATCH + r0]     = v0;
                adj[(size_t)(c0 + 1) * BATCH + r0]     = v1;
                adj[(size_t)c0       * BATCH + r0 + 8] = v2;
                adj[(size_t)(c0 + 1) * BATCH + r0 + 8] = v3;
            }
        }
    }
}

// ---------------------------------------------------------------------------
extern "C" void kernel_launch(void* const* d_in, const int* in_sizes, int n_in,
                              void* d_out, int out_size)
{
    const float* x       = (const float*)d_in[0];
    const float* conv_w  = (const float*)d_in[1];
    const float* conv_b  = (const float*)d_in[2];
    const float* unitary = (const float*)d_in[3];
    const float* lin_w   = (const float*)d_in[4];
    const float* lin_b   = (const float*)d_in[5];
    float* out = (float*)d_out;

    prep_kernel<<<BATCH / 8, 256>>>(x, conv_w, conv_b, unitary, lin_w, lin_b, out);

    cudaFuncSetAttribute(adj_kernel, cudaFuncAttributeMaxDynamicSharedMemorySize, SMEM_DYN);
    adj_kernel<<<NTILE, 256, SMEM_DYN>>>(out + (size_t)BATCH * 10);
}

// round 11
// speedup vs baseline: 2.1708x; 2.1708x over previous
#include <cuda_runtime.h>
#include <cuda_fp16.h>
#include <cstdint>

#define BATCH 8192
#define DFEAT 784
#define KPAD  800          // 25 * 32
#define KC    32
#define NC    25
#define TM    128
#define TN    128
#define STAGES 3
#define NTILE 2080         // 64*65/2 upper-triangular 128x128 tiles

#define A_STAGE_BYTES 8192          // 128 rows * 64 B
#define B_STAGE_BYTES 8192
#define STAGE_BYTES   (A_STAGE_BYTES + B_STAGE_BYTES)
#define SMEM_DYN      (STAGES * STAGE_BYTES)

__device__ __half g_qn[(size_t)BATCH * KPAD];

// ---------------------------------------------------------------------------
// Kernel A (warp-per-image): conv(2x2,s2)+bias -> groupwise 4x4 unitary
//  -> row norm -> fp16 qn scratch; linear head (lin_w in smem) -> log_softmax
// ---------------------------------------------------------------------------
__global__ __launch_bounds__(256) void prep_kernel(
    const float* __restrict__ x, const float* __restrict__ conv_w,
    const float* __restrict__ conv_b, const float* __restrict__ unitary,
    const float* __restrict__ lin_w, const float* __restrict__ lin_b,
    float* __restrict__ out_logp)
{
    __shared__ float lw[7840];        // 10 x 784 linear weights
    __shared__ float xs[8][784];      // per-warp image buffer
    __shared__ float cw[16];
    __shared__ float cb[4];
    __shared__ float U[16];
    __shared__ float lb[10];

    const int tid  = threadIdx.x;
    const int lane = tid & 31;
    const int wid  = tid >> 5;

    for (int i = tid; i < 7840; i += 256) lw[i] = lin_w[i];
    if (tid < 16)               cw[tid]      = conv_w[tid];
    if (tid >= 32 && tid < 36)  cb[tid - 32] = conv_b[tid - 32];
    if (tid >= 64 && tid < 80)  U[tid - 64]  = unitary[tid - 64];
    if (tid >= 96 && tid < 106) lb[tid - 96] = lin_b[tid - 96];
    __syncthreads();

    const int b = blockIdx.x * 8 + wid;

    {
        const float4* x4 = reinterpret_cast<const float4*>(x + (size_t)b * 784);
        float4* s4 = reinterpret_cast<float4*>(xs[wid]);
        for (int i = lane; i < 196; i += 32) s4[i] = x4[i];
    }
    __syncwarp();

    float qv[7][4];
    float ss = 0.f;
    {
        int ng = 0;
        for (int g = lane; g < 196; g += 32, ++ng) {
            const int o  = (4 * g) / 196;
            const int p0 = 4 * g - o * 196;
            float f[4];
#pragma unroll
            for (int u = 0; u < 4; ++u) {
                int p = p0 + u;
                int i = p / 14;
                int j = p - 14 * i;
                const float* xr = xs[wid] + (2 * i) * 28 + 2 * j;
                f[u] = cb[o] + cw[o*4+0]*xr[0]  + cw[o*4+1]*xr[1]
                             + cw[o*4+2]*xr[28] + cw[o*4+3]*xr[29];
            }
#pragma unroll
            for (int w = 0; w < 4; ++w) {
                float v = f[0]*U[w*4+0] + f[1]*U[w*4+1]
                        + f[2]*U[w*4+2] + f[3]*U[w*4+3];
                qv[ng][w] = v;
                ss += v * v;
            }
        }
    }
#pragma unroll
    for (int o = 16; o; o >>= 1) ss += __shfl_xor_sync(0xffffffffu, ss, o);
    const float inv = 1.f / (sqrtf(ss) + 1e-12f);

    // fp16 normalized store, 8B per group
    {
        uint2* dst = reinterpret_cast<uint2*>(g_qn + (size_t)b * KPAD);
        int ng = 0;
        for (int g = lane; g < 196; g += 32, ++ng) {
            __half2 lo = __floats2half2_rn(qv[ng][0]*inv, qv[ng][1]*inv);
            __half2 hi = __floats2half2_rn(qv[ng][2]*inv, qv[ng][3]*inv);
            uint2 pk;
            pk.x = *reinterpret_cast<uint32_t*>(&lo);
            pk.y = *reinterpret_cast<uint32_t*>(&hi);
            dst[g] = pk;
        }
        if (lane < 4) {
            uint2 z; z.x = 0u; z.y = 0u;
            dst[196 + lane] = z;
        }
    }

    float part[10];
#pragma unroll
    for (int c = 0; c < 10; ++c) part[c] = 0.f;
    {
        int ng = 0;
        for (int g = lane; g < 196; g += 32, ++ng) {
#pragma unroll
            for (int c = 0; c < 10; ++c) {
                const float4 w4 = *reinterpret_cast<const float4*>(lw + c * 784 + 4 * g);
                part[c] += qv[ng][0]*w4.x + qv[ng][1]*w4.y
                         + qv[ng][2]*w4.z + qv[ng][3]*w4.w;
            }
        }
    }
#pragma unroll
    for (int c = 0; c < 10; ++c) {
#pragma unroll
        for (int o = 16; o; o >>= 1)
            part[c] += __shfl_xor_sync(0xffffffffu, part[c], o);
    }
    if (lane == 0) {
        float lg[10];
#pragma unroll
        for (int c = 0; c < 10; ++c) lg[c] = part[c] + lb[c];
        float mx = lg[0];
#pragma unroll
        for (int c = 1; c < 10; ++c) mx = fmaxf(mx, lg[c]);
        float s = 0.f;
#pragma unroll
        for (int c = 0; c < 10; ++c) s += expf(lg[c] - mx);
        float lse = mx + logf(s);
#pragma unroll
        for (int c = 0; c < 10; ++c) out_logp[(size_t)b * 10 + c] = lg[c] - lse;
    }
}

// ---------------------------------------------------------------------------
// adj kernel: dense triangular grid of 128x128 tiles, 8 warps of 64x32,
// fp16 mma.sync m16n8k16 with FP16 accumulators (full-rate HMMA),
// 3-stage cp.async pipeline, 2 CTAs/SM.
// ---------------------------------------------------------------------------
__device__ __forceinline__ void ldsm4(uint32_t& r0, uint32_t& r1,
                                      uint32_t& r2, uint32_t& r3, uint32_t addr)
{
    asm volatile("ldmatrix.sync.aligned.m8n8.x4.shared.b16 {%0,%1,%2,%3}, [%4];"
                 : "=r"(r0), "=r"(r1), "=r"(r2), "=r"(r3) : "r"(addr));
}

__device__ __forceinline__ void mma_h(uint32_t* c, const uint32_t* a, const uint32_t* b)
{
    asm volatile("mma.sync.aligned.m16n8k16.row.col.f16.f16.f16.f16 "
                 "{%0,%1}, {%2,%3,%4,%5}, {%6,%7}, {%0,%1};"
                 : "+r"(c[0]), "+r"(c[1])
                 : "r"(a[0]), "r"(a[1]), "r"(a[2]), "r"(a[3]),
                   "r"(b[0]), "r"(b[1]));
}

__device__ __forceinline__ void cpa16(uint32_t s, const void* g) {
    asm volatile("cp.async.cg.shared.global [%0], [%1], 16;" :: "r"(s), "l"(g));
}

__global__ __launch_bounds__(256, 2) void adj_kernel(float* __restrict__ adj)
{
    // decode triangular index -> (br <= bc)
    const int i = blockIdx.x;
    int bc = (int)((sqrtf(8.0f * (float)i + 1.0f) - 1.0f) * 0.5f);
    while ((bc + 1) * (bc + 2) / 2 <= i) ++bc;
    while (bc * (bc + 1) / 2 > i) --bc;
    const int br = i - bc * (bc + 1) / 2;

    extern __shared__ char smem[];
    const uint32_t sBase = (uint32_t)__cvta_generic_to_shared(smem);

    const int tid  = threadIdx.x;
    const int lane = tid & 31;
    const int wid  = tid >> 5;
    const int wm   = wid >> 2;   // 0..1  (64 rows each)
    const int wn   = wid & 3;    // 0..3  (32 cols each)

    uint32_t acc[4][4][2];
#pragma unroll
    for (int a = 0; a < 4; a++)
#pragma unroll
        for (int j = 0; j < 4; j++) {
            acc[a][j][0] = 0u;
            acc[a][j][1] = 0u;
        }

    const __half* gA = g_qn + (size_t)br * TM * KPAD;
    const __half* gB = g_qn + (size_t)bc * TN * KPAD;

    auto load_stage = [&](int s, int c) {
        const uint32_t sa = sBase + s * STAGE_BYTES;
        const uint32_t sb = sa + A_STAGE_BYTES;
        const __half* ga = gA + c * KC;
        const __half* gb = gB + c * KC;
#pragma unroll
        for (int t = 0; t < 2; ++t) {
            int q   = tid + t * 256;
            int row = q >> 2;
            int ch  = q & 3;
            int sw  = ch ^ ((row >> 1) & 3);
            uint32_t so = (uint32_t)(row * 64 + sw * 16);
            cpa16(sa + so, ga + (size_t)row * KPAD + ch * 8);
            cpa16(sb + so, gb + (size_t)row * KPAD + ch * 8);
        }
    };

    auto compute = [&](int s) {
        const uint32_t base_a = sBase + s * STAGE_BYTES;
        const uint32_t base_b = base_a + A_STAGE_BYTES;
#pragma unroll
        for (int ks = 0; ks < KC; ks += 16) {
            uint32_t a[4][4], bb[4][2];
#pragma unroll
            for (int mf = 0; mf < 4; ++mf) {
                int row = wm * 64 + mf * 16 + (lane & 15);
                int col = ks + ((lane >> 4) << 3);
                int ch  = (col >> 3) ^ ((row >> 1) & 3);
                uint32_t addr = base_a + (uint32_t)((row * 32 + ch * 8) * 2);
                ldsm4(a[mf][0], a[mf][1], a[mf][2], a[mf][3], addr);
            }
#pragma unroll
            for (int nf2 = 0; nf2 < 2; ++nf2) {
                int row = wn * 32 + nf2 * 16 + ((lane >> 4) << 3) + (lane & 7);
                int col = ks + ((lane >> 3) & 1) * 8;
                int ch  = (col >> 3) ^ ((row >> 1) & 3);
                uint32_t addr = base_b + (uint32_t)((row * 32 + ch * 8) * 2);
                ldsm4(bb[nf2*2][0], bb[nf2*2][1], bb[nf2*2+1][0], bb[nf2*2+1][1], addr);
            }
#pragma unroll
            for (int mf = 0; mf < 4; ++mf)
#pragma unroll
                for (int nf = 0; nf < 4; ++nf)
                    mma_h(acc[mf][nf], a[mf], bb[nf]);
        }
    };

    load_stage(0, 0);
    asm volatile("cp.async.commit_group;");
    load_stage(1, 1);
    asm volatile("cp.async.commit_group;");

#pragma unroll 1
    for (int c = 0; c < NC; ++c) {
        if (c < NC - 1) asm volatile("cp.async.wait_group 1;");
        else            asm volatile("cp.async.wait_group 0;");
        __syncthreads();
        if (c + 2 < NC) {
            load_stage((c + 2) % STAGES, c + 2);
            asm volatile("cp.async.commit_group;");
        }
        compute(c % STAGES);
    }

    // epilogue: fid = acc^2, threshold, no self edges; mirror for br<bc
    const int g   = lane >> 2;
    const int tig = lane & 3;
#pragma unroll
    for (int mf = 0; mf < 4; ++mf) {
        const int r0 = br * TM + wm * 64 + mf * 16 + g;
#pragma unroll
        for (int nf = 0; nf < 4; ++nf) {
            const int c0 = bc * TN + wn * 32 + nf * 8 + tig * 2;
            const __half2 p01 = *reinterpret_cast<const __half2*>(&acc[mf][nf][0]);
            const __half2 p23 = *reinterpret_cast<const __half2*>(&acc[mf][nf][1]);
            float f0 = __low2float(p01), f1 = __high2float(p01);
            float f2 = __low2float(p23), f3 = __high2float(p23);
            float v0 = (f0 * f0 >= 0.9f && r0     != c0    ) ? 1.f : 0.f;
            float v1 = (f1 * f1 >= 0.9f && r0     != c0 + 1) ? 1.f : 0.f;
            float v2 = (f2 * f2 >= 0.9f && r0 + 8 != c0    ) ? 1.f : 0.f;
            float v3 = (f3 * f3 >= 0.9f && r0 + 8 != c0 + 1) ? 1.f : 0.f;
            *reinterpret_cast<float2*>(&adj[(size_t)r0 * BATCH + c0]) =
                make_float2(v0, v1);
            *reinterpret_cast<float2*>(&adj[(size_t)(r0 + 8) * BATCH + c0]) =
                make_float2(v2, v3);
            if (br != bc) {
                adj[(size_t)c0       * BATCH + r0]     = v0;
                adj[(size_t)(c0 + 1) * BATCH + r0]     = v1;
                adj[(size_t)c0       * BATCH + r0 + 8] = v2;
                adj[(size_t)(c0 + 1) * BATCH + r0 + 8] = v3;
            }
        }
    }
}

// ---------------------------------------------------------------------------
extern "C" void kernel_launch(void* const* d_in, const int* in_sizes, int n_in,
                              void* d_out, int out_size)
{
    const float* x       = (const float*)d_in[0];
    const float* conv_w  = (const float*)d_in[1];
    const float* conv_b  = (const float*)d_in[2];
    const float* unitary = (const float*)d_in[3];
    const float* lin_w   = (const float*)d_in[4];
    const float* lin_b   = (const float*)d_in[5];
    float* out = (float*)d_out;

    prep_kernel<<<BATCH / 8, 256>>>(x, conv_w, conv_b, unitary, lin_w, lin_b, out);

    cudaFuncSetAttribute(adj_kernel, cudaFuncAttributeMaxDynamicSharedMemorySize, SMEM_DYN);
    adj_kernel<<<NTILE, 256, SMEM_DYN>>>(out + (size_t)BATCH * 10);
}

// round 12
// speedup vs baseline: 2.6519x; 1.2216x over previous
#include <cuda_runtime.h>
#include <cuda_fp16.h>
#include <cstdint>

#define BATCH 8192
#define DFEAT 784
#define KPAD  800          // 25 * 32
#define KC    32
#define NC    25
#define NCHK  9            // screening chunks (288 features)
#define TM    128
#define TN    128
#define STAGES 3
#define NTILE 2080         // 64*65/2 upper-triangular 128x128 tiles

#define A_STAGE_BYTES 8192          // 128 rows * 64 B
#define B_STAGE_BYTES 8192
#define STAGE_BYTES   (A_STAGE_BYTES + B_STAGE_BYTES)
#define SMEM_DYN      (STAGES * STAGE_BYTES)

#define THRESH_ABS 0.948683f        // sqrt(0.9)
#define MARGIN     0.05f

__device__ __half g_qn[(size_t)BATCH * KPAD];
__device__ float  g_rr[BATCH];      // per-row tail norm (features 288..783)

// ---------------------------------------------------------------------------
// Kernel A (warp-per-image): conv+unitary -> row norm -> fp16 qn scratch in
// channel-interleaved group order; tail norms; linear head -> log_softmax
// ---------------------------------------------------------------------------
__global__ __launch_bounds__(256) void prep_kernel(
    const float* __restrict__ x, const float* __restrict__ conv_w,
    const float* __restrict__ conv_b, const float* __restrict__ unitary,
    const float* __restrict__ lin_w, const float* __restrict__ lin_b,
    float* __restrict__ out_logp)
{
    __shared__ float lw[7840];
    __shared__ float xs[8][784];
    __shared__ float cw[16];
    __shared__ float cb[4];
    __shared__ float U[16];
    __shared__ float lb[10];

    const int tid  = threadIdx.x;
    const int lane = tid & 31;
    const int wid  = tid >> 5;

    for (int i = tid; i < 7840; i += 256) lw[i] = lin_w[i];
    if (tid < 16)               cw[tid]      = conv_w[tid];
    if (tid >= 32 && tid < 36)  cb[tid - 32] = conv_b[tid - 32];
    if (tid >= 64 && tid < 80)  U[tid - 64]  = unitary[tid - 64];
    if (tid >= 96 && tid < 106) lb[tid - 96] = lin_b[tid - 96];
    __syncthreads();

    const int b = blockIdx.x * 8 + wid;

    {
        const float4* x4 = reinterpret_cast<const float4*>(x + (size_t)b * 784);
        float4* s4 = reinterpret_cast<float4*>(xs[wid]);
        for (int i = lane; i < 196; i += 32) s4[i] = x4[i];
    }
    __syncwarp();

    float qv[7][4];
    float ss = 0.f;
    {
        int ng = 0;
        for (int g = lane; g < 196; g += 32, ++ng) {
            const int o  = (4 * g) / 196;
            const int p0 = 4 * g - o * 196;
            float f[4];
#pragma unroll
            for (int u = 0; u < 4; ++u) {
                int p = p0 + u;
                int i = p / 14;
                int j = p - 14 * i;
                const float* xr = xs[wid] + (2 * i) * 28 + 2 * j;
                f[u] = cb[o] + cw[o*4+0]*xr[0]  + cw[o*4+1]*xr[1]
                             + cw[o*4+2]*xr[28] + cw[o*4+3]*xr[29];
            }
#pragma unroll
            for (int w = 0; w < 4; ++w) {
                float v = f[0]*U[w*4+0] + f[1]*U[w*4+1]
                        + f[2]*U[w*4+2] + f[3]*U[w*4+3];
                qv[ng][w] = v;
                ss += v * v;
            }
        }
    }
#pragma unroll
    for (int o = 16; o; o >>= 1) ss += __shfl_xor_sync(0xffffffffu, ss, o);
    const float inv = 1.f / (sqrtf(ss) + 1e-12f);

    // fp16 store in channel-interleaved group order; accumulate head energy
    float part = 0.f;
    {
        uint2* dst = reinterpret_cast<uint2*>(g_qn + (size_t)b * KPAD);
        int ng = 0;
        for (int g = lane; g < 196; g += 32, ++ng) {
            const float q0 = qv[ng][0]*inv, q1 = qv[ng][1]*inv;
            const float q2 = qv[ng][2]*inv, q3 = qv[ng][3]*inv;
            __half2 lo = __floats2half2_rn(q0, q1);
            __half2 hi = __floats2half2_rn(q2, q3);
            uint2 pk;
            pk.x = *reinterpret_cast<uint32_t*>(&lo);
            pk.y = *reinterpret_cast<uint32_t*>(&hi);
            const int s = (g % 49) * 4 + (g / 49);   // interleave channels
            dst[s] = pk;
            if (s < NCHK * 8) part += q0*q0 + q1*q1 + q2*q2 + q3*q3;
        }
        if (lane < 4) {
            uint2 z; z.x = 0u; z.y = 0u;
            dst[196 + lane] = z;
        }
    }
#pragma unroll
    for (int o = 16; o; o >>= 1) part += __shfl_xor_sync(0xffffffffu, part, o);
    if (lane == 0) g_rr[b] = sqrtf(fmaxf(0.f, 1.0f - part));

    float pt[10];
#pragma unroll
    for (int c = 0; c < 10; ++c) pt[c] = 0.f;
    {
        int ng = 0;
        for (int g = lane; g < 196; g += 32, ++ng) {
#pragma unroll
            for (int c = 0; c < 10; ++c) {
                const float4 w4 = *reinterpret_cast<const float4*>(lw + c * 784 + 4 * g);
                pt[c] += qv[ng][0]*w4.x + qv[ng][1]*w4.y
                       + qv[ng][2]*w4.z + qv[ng][3]*w4.w;
            }
        }
    }
#pragma unroll
    for (int c = 0; c < 10; ++c) {
#pragma unroll
        for (int o = 16; o; o >>= 1)
            pt[c] += __shfl_xor_sync(0xffffffffu, pt[c], o);
    }
    if (lane == 0) {
        float lg[10];
#pragma unroll
        for (int c = 0; c < 10; ++c) lg[c] = pt[c] + lb[c];
        float mx = lg[0];
#pragma unroll
        for (int c = 1; c < 10; ++c) mx = fmaxf(mx, lg[c]);
        float s = 0.f;
#pragma unroll
        for (int c = 0; c < 10; ++c) s += expf(lg[c] - mx);
        float lse = mx + logf(s);
#pragma unroll
        for (int c = 0; c < 10; ++c) out_logp[(size_t)b * 10 + c] = lg[c] - lse;
    }
}

// ---------------------------------------------------------------------------
// adj kernel: fp16-acc HMMA, 128x128 triangular tiles, Cauchy-Schwarz tile
// screening after NCHK chunks -> skip tail + zero-fill for far pairs.
// ---------------------------------------------------------------------------
__device__ __forceinline__ void ldsm4(uint32_t& r0, uint32_t& r1,
                                      uint32_t& r2, uint32_t& r3, uint32_t addr)
{
    asm volatile("ldmatrix.sync.aligned.m8n8.x4.shared.b16 {%0,%1,%2,%3}, [%4];"
                 : "=r"(r0), "=r"(r1), "=r"(r2), "=r"(r3) : "r"(addr));
}

__device__ __forceinline__ void mma_h(uint32_t* c, const uint32_t* a, const uint32_t* b)
{
    asm volatile("mma.sync.aligned.m16n8k16.row.col.f16.f16.f16.f16 "
                 "{%0,%1}, {%2,%3,%4,%5}, {%6,%7}, {%0,%1};"
                 : "+r"(c[0]), "+r"(c[1])
                 : "r"(a[0]), "r"(a[1]), "r"(a[2]), "r"(a[3]),
                   "r"(b[0]), "r"(b[1]));
}

__device__ __forceinline__ void cpa16(uint32_t s, const void* g) {
    asm volatile("cp.async.cg.shared.global [%0], [%1], 16;" :: "r"(s), "l"(g));
}

__global__ __launch_bounds__(256, 2) void adj_kernel(float* __restrict__ adj)
{
    const int i = blockIdx.x;
    int bc = (int)((sqrtf(8.0f * (float)i + 1.0f) - 1.0f) * 0.5f);
    while ((bc + 1) * (bc + 2) / 2 <= i) ++bc;
    while (bc * (bc + 1) / 2 > i) --bc;
    const int br = i - bc * (bc + 1) / 2;

    extern __shared__ char smem[];
    const uint32_t sBase = (uint32_t)__cvta_generic_to_shared(smem);

    __shared__ float red[8];
    __shared__ float restAB;
    __shared__ int   skipflag;

    const int tid  = threadIdx.x;
    const int lane = tid & 31;
    const int wid  = tid >> 5;
    const int wm   = wid >> 2;
    const int wn   = wid & 3;

    // tile tail-norm bound: max over A rows * max over B rows
    {
        float rv = (tid < 128) ? g_rr[br * TM + tid] : g_rr[bc * TN + (tid - 128)];
#pragma unroll
        for (int o = 16; o; o >>= 1) rv = fmaxf(rv, __shfl_xor_sync(0xffffffffu, rv, o));
        if (lane == 0) red[wid] = rv;
    }
    __syncthreads();
    if (tid == 0) {
        float ma = fmaxf(fmaxf(red[0], red[1]), fmaxf(red[2], red[3]));
        float mb = fmaxf(fmaxf(red[4], red[5]), fmaxf(red[6], red[7]));
        restAB = ma * mb;
    }

    uint32_t acc[4][4][2];
#pragma unroll
    for (int a = 0; a < 4; a++)
#pragma unroll
        for (int j = 0; j < 4; j++) { acc[a][j][0] = 0u; acc[a][j][1] = 0u; }

    const __half* gA = g_qn + (size_t)br * TM * KPAD;
    const __half* gB = g_qn + (size_t)bc * TN * KPAD;

    auto load_stage = [&](int s, int c) {
        const uint32_t sa = sBase + s * STAGE_BYTES;
        const uint32_t sb = sa + A_STAGE_BYTES;
        const __half* ga = gA + c * KC;
        const __half* gb = gB + c * KC;
#pragma unroll
        for (int t = 0; t < 2; ++t) {
            int q   = tid + t * 256;
            int row = q >> 2;
            int ch  = q & 3;
            int sw  = ch ^ ((row >> 1) & 3);
            uint32_t so = (uint32_t)(row * 64 + sw * 16);
            cpa16(sa + so, ga + (size_t)row * KPAD + ch * 8);
            cpa16(sb + so, gb + (size_t)row * KPAD + ch * 8);
        }
    };

    auto compute = [&](int s) {
        const uint32_t base_a = sBase + s * STAGE_BYTES;
        const uint32_t base_b = base_a + A_STAGE_BYTES;
#pragma unroll
        for (int ks = 0; ks < KC; ks += 16) {
            uint32_t a[4][4], bb[4][2];
#pragma unroll
            for (int mf = 0; mf < 4; ++mf) {
                int row = wm * 64 + mf * 16 + (lane & 15);
                int col = ks + ((lane >> 4) << 3);
                int ch  = (col >> 3) ^ ((row >> 1) & 3);
                uint32_t addr = base_a + (uint32_t)((row * 32 + ch * 8) * 2);
                ldsm4(a[mf][0], a[mf][1], a[mf][2], a[mf][3], addr);
            }
#pragma unroll
            for (int nf2 = 0; nf2 < 2; ++nf2) {
                int row = wn * 32 + nf2 * 16 + ((lane >> 4) << 3) + (lane & 7);
                int col = ks + ((lane >> 3) & 1) * 8;
                int ch  = (col >> 3) ^ ((row >> 1) & 3);
                uint32_t addr = base_b + (uint32_t)((row * 32 + ch * 8) * 2);
                ldsm4(bb[nf2*2][0], bb[nf2*2][1], bb[nf2*2+1][0], bb[nf2*2+1][1], addr);
            }
#pragma unroll
            for (int mf = 0; mf < 4; ++mf)
#pragma unroll
                for (int nf = 0; nf < 4; ++nf)
                    mma_h(acc[mf][nf], a[mf], bb[nf]);
        }
    };

    // ---- phase 1: screening chunks 0..NCHK-1 ----
    load_stage(0, 0);
    asm volatile("cp.async.commit_group;");
    load_stage(1, 1);
    asm volatile("cp.async.commit_group;");

#pragma unroll 1
    for (int c = 0; c < NCHK; ++c) {
        if (c < NCHK - 1) asm volatile("cp.async.wait_group 1;");
        else              asm volatile("cp.async.wait_group 0;");
        __syncthreads();
        if (c + 2 < NCHK) {
            load_stage((c + 2) % STAGES, c + 2);
            asm volatile("cp.async.commit_group;");
        }
        compute(c % STAGES);
    }

    // ---- screening decision ----
    {
        float tmax = 0.f;
#pragma unroll
        for (int mf = 0; mf < 4; ++mf)
#pragma unroll
            for (int nf = 0; nf < 4; ++nf) {
                const __half2 p01 = *reinterpret_cast<const __half2*>(&acc[mf][nf][0]);
                const __half2 p23 = *reinterpret_cast<const __half2*>(&acc[mf][nf][1]);
                tmax = fmaxf(tmax, fmaxf(fabsf(__low2float(p01)), fabsf(__high2float(p01))));
                tmax = fmaxf(tmax, fmaxf(fabsf(__low2float(p23)), fabsf(__high2float(p23))));
            }
#pragma unroll
        for (int o = 16; o; o >>= 1) tmax = fmaxf(tmax, __shfl_xor_sync(0xffffffffu, tmax, o));
        if (lane == 0) red[wid] = tmax;
        __syncthreads();
        if (tid == 0) {
            float m = red[0];
#pragma unroll
            for (int w = 1; w < 8; ++w) m = fmaxf(m, red[w]);
            skipflag = (m + restAB + MARGIN < THRESH_ABS) ? 1 : 0;
        }
        __syncthreads();
    }

    if (skipflag) {
        // whole tile below threshold: write zeros (both orientations)
        const float4 z = make_float4(0.f, 0.f, 0.f, 0.f);
#pragma unroll 1
        for (int rr = 0; rr < 16; ++rr) {
            const int r = wid * 16 + rr;
            *reinterpret_cast<float4*>(
                adj + (size_t)(br * TM + r) * BATCH + bc * TN + 4 * lane) = z;
            if (br != bc)
                *reinterpret_cast<float4*>(
                    adj + (size_t)(bc * TN + r) * BATCH + br * TM + 4 * lane) = z;
        }
        return;
    }

    // ---- phase 2: remaining chunks NCHK..NC-1 ----
    load_stage(NCHK % STAGES, NCHK);
    asm volatile("cp.async.commit_group;");
    load_stage((NCHK + 1) % STAGES, NCHK + 1);
    asm volatile("cp.async.commit_group;");

#pragma unroll 1
    for (int c = NCHK; c < NC; ++c) {
        if (c < NC - 1) asm volatile("cp.async.wait_group 1;");
        else            asm volatile("cp.async.wait_group 0;");
        __syncthreads();
        if (c + 2 < NC) {
            load_stage((c + 2) % STAGES, c + 2);
            asm volatile("cp.async.commit_group;");
        }
        compute(c % STAGES);
    }

    // epilogue
    const int g   = lane >> 2;
    const int tig = lane & 3;
#pragma unroll
    for (int mf = 0; mf < 4; ++mf) {
        const int r0 = br * TM + wm * 64 + mf * 16 + g;
#pragma unroll
        for (int nf = 0; nf < 4; ++nf) {
            const int c0 = bc * TN + wn * 32 + nf * 8 + tig * 2;
            const __half2 p01 = *reinterpret_cast<const __half2*>(&acc[mf][nf][0]);
            const __half2 p23 = *reinterpret_cast<const __half2*>(&acc[mf][nf][1]);
            float f0 = __low2float(p01), f1 = __high2float(p01);
            float f2 = __low2float(p23), f3 = __high2float(p23);
            float v0 = (f0 * f0 >= 0.9f && r0     != c0    ) ? 1.f : 0.f;
            float v1 = (f1 * f1 >= 0.9f && r0     != c0 + 1) ? 1.f : 0.f;
            float v2 = (f2 * f2 >= 0.9f && r0 + 8 != c0    ) ? 1.f : 0.f;
            float v3 = (f3 * f3 >= 0.9f && r0 + 8 != c0 + 1) ? 1.f : 0.f;
            *reinterpret_cast<float2*>(&adj[(size_t)r0 * BATCH + c0]) =
                make_float2(v0, v1);
            *reinterpret_cast<float2*>(&adj[(size_t)(r0 + 8) * BATCH + c0]) =
                make_float2(v2, v3);
            if (br != bc) {
                adj[(size_t)c0       * BATCH + r0]     = v0;
                adj[(size_t)(c0 + 1) * BATCH + r0]     = v1;
                adj[(size_t)c0       * BATCH + r0 + 8] = v2;
                adj[(size_t)(c0 + 1) * BATCH + r0 + 8] = v3;
            }
        }
    }
}

// ---------------------------------------------------------------------------
extern "C" void kernel_launch(void* const* d_in, const int* in_sizes, int n_in,
                              void* d_out, int out_size)
{
    const float* x       = (const float*)d_in[0];
    const float* conv_w  = (const float*)d_in[1];
    const float* conv_b  = (const float*)d_in[2];
    const float* unitary = (const float*)d_in[3];
    const float* lin_w   = (const float*)d_in[4];
    const float* lin_b   = (const float*)d_in[5];
    float* out = (float*)d_out;

    prep_kernel<<<BATCH / 8, 256>>>(x, conv_w, conv_b, unitary, lin_w, lin_b, out);

    cudaFuncSetAttribute(adj_kernel, cudaFuncAttributeMaxDynamicSharedMemorySize, SMEM_DYN);
    adj_kernel<<<NTILE, 256, SMEM_DYN>>>(out + (size_t)BATCH * 10);
}